// round 9
// baseline (speedup 1.0000x reference)
#include <cuda_runtime.h>
#include <cuda_fp16.h>
#include <math.h>
#include <stdint.h>

#define BATCH 32
#define SEQ   2048
#define DQ    1024
#define DV    1024
#define UN    1024
#define ROWS  (BATCH * SEQ)

#define BM 128
#define BN 128
#define CHUNK_A 8192
#define CHUNK_B 8192
#define NCHUNK (DV / 32)              // 32 sub-chunks
#define NSTEP  16                     // stages per tile (64-k each)
#define STAGE_BYTES 32768             // A 16K | B 16K
#define NSTAGE 3
#define RED_BYTES 2048
#define SMEM_BYTES (1024 + RED_BYTES + NSTAGE * STAGE_BYTES)   // 101376
#define NTILES 4096                   // 8 u-tiles x 512 row-tiles
#define GRID_P 296                    // 148 SMs x 2 CTAs
#define NCTX 64

// ---------------- device scratch ------------------------------------------
__device__ unsigned char g_at[(size_t)(ROWS / BM) * NCHUNK * CHUNK_A];  // 128MB
__device__ unsigned char g_bt[(size_t)(UN / BN) * NCHUNK * CHUNK_B];    // 2MB
__device__ float g_projq[BATCH * UN];
__device__ float g_spart[(size_t)ROWS * 8];
__device__ float g_cpart[(size_t)NCTX * BATCH * DV];

// ---------------- helpers ---------------------------------------------------
__device__ __forceinline__ uint32_t smem_u32(const void* p) {
    uint32_t a;
    asm("{ .reg .u64 t; cvta.to.shared.u64 t, %1; cvt.u32.u64 %0, t; }" : "=r"(a) : "l"(p));
    return a;
}
#define MBARRIER_INIT(addr, cnt) \
    asm volatile("mbarrier.init.shared.b64 [%0], %1;" :: "r"((uint32_t)(addr)), "r"((uint32_t)(cnt)) : "memory")
#define MBARRIER_ARRIVE(addr) \
    asm volatile("mbarrier.arrive.shared.b64 _, [%0];" :: "r"((uint32_t)(addr)) : "memory")
#define MBARRIER_EXPECT_TX(addr, tx) \
    asm volatile("mbarrier.arrive.expect_tx.shared.b64 _, [%0], %1;" :: "r"((uint32_t)(addr)), "r"((uint32_t)(tx)) : "memory")
#define MBARRIER_WAIT(addr, ph) do { \
    uint32_t _m = (uint32_t)(addr), _p = (uint32_t)(ph), _d; \
    asm volatile("{\n\t.reg .pred p;\n\t" \
        "mbarrier.try_wait.parity.acquire.cta.shared::cta.b64 p, [%1], %2;\n\t" \
        "selp.b32 %0, 1, 0, p;\n\t}" : "=r"(_d) : "r"(_m), "r"(_p) : "memory"); \
    if (!_d) { \
        asm volatile("{\n\t.reg .pred P1;\n\t" \
            "WL_%=:\n\t" \
            "mbarrier.try_wait.parity.acquire.cta.shared::cta.b64 P1, [%0], %1, 0x989680;\n\t" \
            "@P1 bra.uni WD_%=;\n\t" \
            "bra.uni WL_%=;\n\t" \
            "WD_%=:\n\t}" :: "r"(_m), "r"(_p) : "memory"); \
    } \
} while (0)
#define FENCE_PROXY_ASYNC() asm volatile("fence.proxy.async.shared::cta;" ::: "memory")
#define BAR_COMPUTE() asm volatile("bar.sync 1, 256;" ::: "memory")
__device__ __forceinline__ void cp_bulk(uint32_t dst, const void* src, uint32_t bytes,
                                        uint32_t mbar) {
    asm volatile("cp.async.bulk.shared::cta.global.mbarrier::complete_tx::bytes "
                 "[%0], [%1], %2, [%3];"
                 :: "r"(dst), "l"(src), "r"(bytes), "r"(mbar) : "memory");
}
#define LDSM_X4(R, addr) \
    asm volatile("ldmatrix.sync.aligned.m8n8.x4.shared.b16 {%0,%1,%2,%3}, [%4];" \
        : "=r"((R)[0]), "=r"((R)[1]), "=r"((R)[2]), "=r"((R)[3]) : "r"(addr))
#define MMA16816(C, A, B0, B1) \
    asm volatile("mma.sync.aligned.m16n8k16.row.col.f32.f16.f16.f32 " \
        "{%0,%1,%2,%3},{%4,%5,%6,%7},{%8,%9},{%0,%1,%2,%3};" \
        : "+f"((C)[0]), "+f"((C)[1]), "+f"((C)[2]), "+f"((C)[3]) \
        : "r"((A)[0]), "r"((A)[1]), "r"((A)[2]), "r"((A)[3]), "r"(B0), "r"(B1))

// SW64 swizzle: 64B rows; 16B chunk c of row r -> c ^ ((r>>1)&3)
__device__ __forceinline__ uint32_t sw64_off(int row, int c) {
    return (uint32_t)(row * 64 + ((c ^ ((row >> 1) & 3)) << 4));
}

// MUFU-free tanh (FMA/ALU only), abs err ~2e-6
__device__ __forceinline__ float tanh_fma(float x) {
    float ax = fabsf(x);
    float y  = fminf(ax * 2.885390082f, 24.0f);
    float r  = y + 12582912.0f;
    int   ki = __float_as_int(r) - 0x4B400000;
    float f  = y - (r - 12582912.0f);
    float p  = 1.33218890e-3f;
    p = fmaf(p, f, 9.61812910e-3f);
    p = fmaf(p, f, 5.55041087e-2f);
    p = fmaf(p, f, 2.40226507e-1f);
    p = fmaf(p, f, 6.93147181e-1f);
    p = fmaf(p, f, 1.0f);
    float e   = __int_as_float(__float_as_int(p) + (ki << 23));
    float den = e + 1.0f;
    float z   = __int_as_float(0x7EF311C3 - __float_as_int(den));
    z = z * fmaf(-den, z, 2.0f);
    z = z * fmaf(-den, z, 2.0f);
    z = z * fmaf(-den, z, 2.0f);
    float t = fmaf(-2.0f, z, 1.0f);
    return copysignf(t, x);
}

// ---------------------------------------------------------------------------
__global__ void split_values_kernel(const float* __restrict__ v) {
    size_t i = ((size_t)blockIdx.x * 256 + threadIdx.x) * 4;
    float4 x = *(const float4*)(v + i);
    const int row = (int)(i >> 10), col = (int)(i & 1023);
    const int rb = row >> 7, r = row & 127;
    const int ch = col >> 5,  ci = col & 31;
    const int sw = (ci >> 3) ^ ((r >> 1) & 3);
    unsigned char* base = g_at + ((size_t)(rb * NCHUNK + ch) * CHUNK_A)
                               + r * 64 + sw * 16 + (ci & 7) * 2;
    __half2 a = __halves2half2(__float2half_rn(x.x), __float2half_rn(x.y));
    __half2 b = __halves2half2(__float2half_rn(x.z), __float2half_rn(x.w));
    uint2 hi;
    hi.x = *(uint32_t*)&a; hi.y = *(uint32_t*)&b;
    *(uint2*)base = hi;
}

__global__ void split_w1t_kernel(const float* __restrict__ W1) {
    __shared__ float t[32][33];
    const int bx = blockIdx.x * 32, by = blockIdx.y * 32;
    const int tx = threadIdx.x, ty = threadIdx.y;
#pragma unroll
    for (int rr = 0; rr < 4; ++rr)
        t[ty + 8 * rr][tx] = W1[(size_t)(by + ty + 8 * rr) * UN + bx + tx];
    __syncthreads();
    const int u = bx + tx, k0 = by + ty * 4;
    float4 x;
    x.x = t[ty * 4 + 0][tx]; x.y = t[ty * 4 + 1][tx];
    x.z = t[ty * 4 + 2][tx]; x.w = t[ty * 4 + 3][tx];
    const int ut = u >> 7, r = u & 127;
    const int ch = k0 >> 5, ci = k0 & 31;
    const int sw = (ci >> 3) ^ ((r >> 1) & 3);
    unsigned char* base = g_bt + ((size_t)(ut * NCHUNK + ch) * CHUNK_B)
                               + r * 64 + sw * 16 + (ci & 7) * 2;
    __half2 a = __halves2half2(__float2half_rn(x.x), __float2half_rn(x.y));
    __half2 b = __halves2half2(__float2half_rn(x.z), __float2half_rn(x.w));
    uint2 hi;
    hi.x = *(uint32_t*)&a; hi.y = *(uint32_t*)&b;
    *(uint2*)base = hi;
}

__global__ void projq_kernel(const float* __restrict__ q,
                             const float* __restrict__ W2,
                             const float* __restrict__ b2) {
    const int u = blockIdx.x * 256 + threadIdx.x;
    const int b = blockIdx.y;
    const float* qb = q + b * DQ;
    float acc = b2[u];
#pragma unroll 8
    for (int d = 0; d < DQ; ++d)
        acc = fmaf(qb[d], W2[(size_t)d * UN + u], acc);
    g_projq[b * UN + u] = acc;
}

// ---------------------------------------------------------------------------
// score: persistent CTAs, fp16 HMMA, streaming 3-stage pipeline across tiles.
// 288 threads: warps 0-7 compute, warp 8 producer. Grid = 296.
// ---------------------------------------------------------------------------
__global__ __launch_bounds__(288, 2) void score_kernel(
    const float* __restrict__ b1g, const float* __restrict__ Vv) {

    extern __shared__ char smem[];
    const uint32_t sb    = smem_u32(smem);
    const uint32_t FULLB = sb;           // full[st]  at sb + st*8
    const uint32_t EMPTB = sb + 24;      // empty[st] at sb + 24 + st*8
    float* red           = (float*)(smem + 1024);
    const uint32_t SDATA = sb + 1024 + RED_BYTES;

    const int tid = threadIdx.x, wid = tid >> 5, lane = tid & 31;
    const int cta = blockIdx.x;

    // static tile schedule: CTAs 0..247 get 14 tiles, 248..295 get 13
    const int ntiles = (cta < 248) ? 14 : 13;
    const int start  = (cta < 248) ? cta * 14 : 3472 + (cta - 248) * 13;

    if (tid == 0) {
#pragma unroll
        for (int st = 0; st < NSTAGE; ++st) {
            MBARRIER_INIT(FULLB + st * 8, 1);
            MBARRIER_INIT(EMPTB + st * 8, 8);
        }
        FENCE_PROXY_ASYNC();
    }
    __syncthreads();

    if (wid == 8) {
        // ---------------- producer warp: streams all tiles ------------------
        if (lane == 0) {
            int st = 0, r = 0, gs = 0;
            for (int t = 0; t < ntiles; ++t) {
                const int tile = start + t;
                const unsigned char* gA =
                    g_at + (size_t)(tile >> 3) * (NCHUNK * CHUNK_A);
                const unsigned char* gB =
                    g_bt + (size_t)(tile & 7) * (NCHUNK * CHUNK_B);
                for (int sstep = 0; sstep < NSTEP; ++sstep, ++gs) {
                    if (gs >= NSTAGE) MBARRIER_WAIT(EMPTB + st * 8, (r - 1) & 1);
                    const uint32_t dst = SDATA + st * STAGE_BYTES;
                    MBARRIER_EXPECT_TX(FULLB + st * 8, STAGE_BYTES);
                    cp_bulk(dst,         gA + (size_t)sstep * 16384, 16384,
                            FULLB + st * 8);
                    cp_bulk(dst + 16384, gB + (size_t)sstep * 16384, 16384,
                            FULLB + st * 8);
                    if (++st == NSTAGE) { st = 0; ++r; }
                }
            }
        }
    } else {
        // ---------------- compute warps -------------------------------------
        const int warp_m = wid & 1, warp_n = wid >> 1;
        const int lr = lane & 15, lh = lane >> 4;
        uint32_t aoff[4], boff[2];
#pragma unroll
        for (int mt = 0; mt < 4; ++mt)
            aoff[mt] = sw64_off(warp_m * 64 + mt * 16 + lr, lh);
#pragma unroll
        for (int bt = 0; bt < 2; ++bt)
            boff[bt] = sw64_off(warp_n * 32 + bt * 16 + lr, lh);

        int st = 0, rnd = 0;
        for (int t = 0; t < ntiles; ++t) {
            const int tile = start + t;
            const int u0   = (tile & 7) * BN;
            const int row0 = (tile >> 3) * BM;
            const int b    = row0 >> 11;

            float acc[4][4][4];
#pragma unroll
            for (int i = 0; i < 4; ++i)
#pragma unroll
                for (int j = 0; j < 4; ++j)
#pragma unroll
                    for (int k = 0; k < 4; ++k) acc[i][j][k] = 0.0f;

            for (int s = 0; s < NSTEP; ++s) {
                const uint32_t sb_cp = SDATA + st * STAGE_BYTES;
                MBARRIER_WAIT(FULLB + st * 8, rnd & 1);

#pragma unroll
                for (int kslice = 0; kslice < 4; ++kslice) {
                    const uint32_t sub = (kslice >> 1) * 8192;
                    const uint32_t kx  = (kslice & 1) << 5;
                    const uint32_t abase = sb_cp + sub;
                    uint32_t a[4][4], bh[2][4];
#pragma unroll
                    for (int mt = 0; mt < 4; ++mt)
                        LDSM_X4(a[mt], abase + (aoff[mt] ^ kx));
#pragma unroll
                    for (int bt = 0; bt < 2; ++bt)
                        LDSM_X4(bh[bt], abase + 16384 + (boff[bt] ^ kx));
#pragma unroll
                    for (int mt = 0; mt < 4; ++mt)
#pragma unroll
                        for (int nt = 0; nt < 4; ++nt)
                            MMA16816(acc[mt][nt], a[mt],
                                     bh[nt >> 1][nt & 1],
                                     bh[nt >> 1][(nt & 1) + 2]);
                }
                if (lane == 0) MBARRIER_ARRIVE(EMPTB + st * 8);
                if (++st == NSTAGE) { st = 0; ++rnd; }
            }

            // ------------ fused epilogue (overlaps next tile's prefetch) ----
            float tb[8], tv[8];
#pragma unroll
            for (int nt = 0; nt < 4; ++nt)
#pragma unroll
                for (int par = 0; par < 2; ++par) {
                    const int u = u0 + warp_n * 32 + nt * 8 + (lane & 3) * 2 + par;
                    tb[nt * 2 + par] = b1g[u] + g_projq[b * UN + u];
                    tv[nt * 2 + par] = Vv[u];
                }

#pragma unroll
            for (int mt = 0; mt < 4; ++mt) {
                float s0 = 0.0f, s1 = 0.0f;
#pragma unroll
                for (int nt = 0; nt < 4; ++nt)
#pragma unroll
                    for (int par = 0; par < 2; ++par) {
                        const int j = nt * 2 + par;
                        s0 = fmaf(tanh_fma(acc[mt][nt][par]     + tb[j]), tv[j], s0);
                        s1 = fmaf(tanh_fma(acc[mt][nt][2 + par] + tb[j]), tv[j], s1);
                    }
                s0 += __shfl_xor_sync(0xffffffff, s0, 1);
                s0 += __shfl_xor_sync(0xffffffff, s0, 2);
                s1 += __shfl_xor_sync(0xffffffff, s1, 1);
                s1 += __shfl_xor_sync(0xffffffff, s1, 2);
                if ((lane & 3) == 0) {
                    const int r = warp_m * 64 + mt * 16 + (lane >> 2);
                    red[r * 4 + warp_n]       = s0;
                    red[(r + 8) * 4 + warp_n] = s1;
                }
            }
            BAR_COMPUTE();
            if (tid < 128) {
                const float s = (red[tid * 4 + 0] + red[tid * 4 + 1]) +
                                (red[tid * 4 + 2] + red[tid * 4 + 3]);
                g_spart[(size_t)(row0 + tid) * 8 + (tile & 7)] = s;
            }
            BAR_COMPUTE();
        }
    }
}

// ---------------------------------------------------------------------------
__global__ void softmax_kernel(float* __restrict__ out_w) {
    const int b = blockIdx.x, tid = threadIdx.x;
    __shared__ float sm[256];
    float v[8];
    float lmax = -1e30f;
#pragma unroll
    for (int i = 0; i < 8; ++i) {
        const float* p = g_spart + (size_t)(b * SEQ + tid + i * 256) * 8;
        v[i] = ((p[0] + p[1]) + (p[2] + p[3])) + ((p[4] + p[5]) + (p[6] + p[7]));
        lmax = fmaxf(lmax, v[i]);
    }
    sm[tid] = lmax; __syncthreads();
    for (int s = 128; s > 0; s >>= 1) {
        if (tid < s) sm[tid] = fmaxf(sm[tid], sm[tid + s]);
        __syncthreads();
    }
    const float m = sm[0]; __syncthreads();
    float lsum = 0.0f;
#pragma unroll
    for (int i = 0; i < 8; ++i) { v[i] = __expf(v[i] - m); lsum += v[i]; }
    sm[tid] = lsum; __syncthreads();
    for (int s = 128; s > 0; s >>= 1) {
        if (tid < s) sm[tid] += sm[tid + s];
        __syncthreads();
    }
    const float inv = 1.0f / sm[0];
#pragma unroll
    for (int i = 0; i < 8; ++i)
        out_w[b * SEQ + tid + i * 256] = v[i] * inv;
}

// ---------------------------------------------------------------------------
__global__ void ctx_part_kernel(const float* __restrict__ values,
                                const float* __restrict__ w) {
    __shared__ float ws[32];
    const int sc = blockIdx.x, b = blockIdx.y, tid = threadIdx.x;
    if (tid < 32) ws[tid] = w[b * SEQ + sc * 32 + tid];
    __syncthreads();
    const int d0 = tid * 4;
    const float* base = values + (size_t)b * SEQ * DV + (size_t)sc * 32 * DV + d0;
    float4 acc = make_float4(0.f, 0.f, 0.f, 0.f);
#pragma unroll 8
    for (int s = 0; s < 32; ++s) {
        const float4 v = *(const float4*)(base + (size_t)s * DV);
        const float x = ws[s];
        acc.x = fmaf(x, v.x, acc.x); acc.y = fmaf(x, v.y, acc.y);
        acc.z = fmaf(x, v.z, acc.z); acc.w = fmaf(x, v.w, acc.w);
    }
    *(float4*)(g_cpart + (size_t)(sc * BATCH + b) * DV + d0) = acc;
}

__global__ void ctx_reduce_kernel(float* __restrict__ out_c) {
    const int idx = blockIdx.x * 256 + threadIdx.x;
    const int bb = idx >> 10, dd = idx & 1023;
    float s = 0.0f;
#pragma unroll 8
    for (int c = 0; c < NCTX; ++c)
        s += g_cpart[(size_t)(c * BATCH + bb) * DV + dd];
    out_c[idx] = s;
}

// ---------------------------------------------------------------------------
extern "C" void kernel_launch(void* const* d_in, const int* in_sizes, int n_in,
                              void* d_out, int out_size) {
    const float* query  = (const float*)d_in[0];
    const float* values = (const float*)d_in[1];
    const float* W1     = (const float*)d_in[2];
    const float* b1     = (const float*)d_in[3];
    const float* W2     = (const float*)d_in[4];
    const float* b2     = (const float*)d_in[5];
    const float* Vv     = (const float*)d_in[6];
    // d_in[7] = bV: cancels in softmax.

    float* out_c = (float*)d_out;
    float* out_w = out_c + BATCH * DV;

    static bool attr_set = false;
    if (!attr_set) {
        cudaFuncSetAttribute(score_kernel,
                             cudaFuncAttributeMaxDynamicSharedMemorySize, SMEM_BYTES);
        attr_set = true;
    }

    split_values_kernel<<<65536, 256>>>(values);
    split_w1t_kernel<<<dim3(32, 32), dim3(32, 8)>>>(W1);
    projq_kernel<<<dim3(4, BATCH), 256>>>(query, W2, b2);
    score_kernel<<<GRID_P, 288, SMEM_BYTES>>>(b1, Vv);
    softmax_kernel<<<BATCH, 256>>>(out_w);
    ctx_part_kernel<<<dim3(NCTX, BATCH), 256>>>(values, out_w);
    ctx_reduce_kernel<<<128, 256>>>(out_c);
}

// round 10
// speedup vs baseline: 1.0846x; 1.0846x over previous
#include <cuda_runtime.h>
#include <cuda_fp16.h>
#include <math.h>
#include <stdint.h>

#define BATCH 32
#define SEQ   2048
#define DQ    1024
#define DV    1024
#define UN    1024
#define ROWS  (BATCH * SEQ)

#define BM 128
#define BN 128
#define CHUNK_A 8192                  // per 32-k sub-chunk
#define CHUNK_B 8192
#define NCHUNK (DV / 32)              // 32 sub-chunks
#define NSTEP  16                     // stages consumed (2 sub-chunks each)
#define STAGE_BYTES 32768             // A 16K | B 16K
#define NSTAGE 3
#define SMEM_BYTES (1024 + NSTAGE * STAGE_BYTES)   // 99328
#define NCTX 64

// ---------------- device scratch ------------------------------------------
__device__ unsigned char g_at[(size_t)(ROWS / BM) * NCHUNK * CHUNK_A];  // 128MB
__device__ unsigned char g_bt[(size_t)(UN / BN) * NCHUNK * CHUNK_B];    // 2MB
__device__ float g_projq[BATCH * UN];
__device__ float g_spart[(size_t)ROWS * 8];
__device__ float g_cpart[(size_t)NCTX * BATCH * DV];

// ---------------- helpers ---------------------------------------------------
__device__ __forceinline__ uint32_t smem_u32(const void* p) {
    uint32_t a;
    asm("{ .reg .u64 t; cvta.to.shared.u64 t, %1; cvt.u32.u64 %0, t; }" : "=r"(a) : "l"(p));
    return a;
}
#define MBARRIER_INIT(addr, cnt) \
    asm volatile("mbarrier.init.shared.b64 [%0], %1;" :: "r"((uint32_t)(addr)), "r"((uint32_t)(cnt)) : "memory")
#define MBARRIER_ARRIVE(addr) \
    asm volatile("mbarrier.arrive.shared.b64 _, [%0];" :: "r"((uint32_t)(addr)) : "memory")
#define MBARRIER_EXPECT_TX(addr, tx) \
    asm volatile("mbarrier.arrive.expect_tx.shared.b64 _, [%0], %1;" :: "r"((uint32_t)(addr)), "r"((uint32_t)(tx)) : "memory")
#define MBARRIER_WAIT(addr, ph) do { \
    uint32_t _m = (uint32_t)(addr), _p = (uint32_t)(ph), _d; \
    asm volatile("{\n\t.reg .pred p;\n\t" \
        "mbarrier.try_wait.parity.acquire.cta.shared::cta.b64 p, [%1], %2;\n\t" \
        "selp.b32 %0, 1, 0, p;\n\t}" : "=r"(_d) : "r"(_m), "r"(_p) : "memory"); \
    if (!_d) { \
        asm volatile("{\n\t.reg .pred P1;\n\t" \
            "WL_%=:\n\t" \
            "mbarrier.try_wait.parity.acquire.cta.shared::cta.b64 P1, [%0], %1, 0x989680;\n\t" \
            "@P1 bra.uni WD_%=;\n\t" \
            "bra.uni WL_%=;\n\t" \
            "WD_%=:\n\t}" :: "r"(_m), "r"(_p) : "memory"); \
    } \
} while (0)
#define FENCE_PROXY_ASYNC() asm volatile("fence.proxy.async.shared::cta;" ::: "memory")
__device__ __forceinline__ void cp_bulk(uint32_t dst, const void* src, uint32_t bytes,
                                        uint32_t mbar) {
    asm volatile("cp.async.bulk.shared::cta.global.mbarrier::complete_tx::bytes "
                 "[%0], [%1], %2, [%3];"
                 :: "r"(dst), "l"(src), "r"(bytes), "r"(mbar) : "memory");
}
#define LDSM_X4(R, addr) \
    asm volatile("ldmatrix.sync.aligned.m8n8.x4.shared.b16 {%0,%1,%2,%3}, [%4];" \
        : "=r"((R)[0]), "=r"((R)[1]), "=r"((R)[2]), "=r"((R)[3]) : "r"(addr))
#define MMA16816(C, A, B0, B1) \
    asm volatile("mma.sync.aligned.m16n8k16.row.col.f32.f16.f16.f32 " \
        "{%0,%1,%2,%3},{%4,%5,%6,%7},{%8,%9},{%0,%1,%2,%3};" \
        : "+f"((C)[0]), "+f"((C)[1]), "+f"((C)[2]), "+f"((C)[3]) \
        : "r"((A)[0]), "r"((A)[1]), "r"((A)[2]), "r"((A)[3]), "r"(B0), "r"(B1))

// SW64 swizzle: 64B rows; 16B chunk c of row r -> c ^ ((r>>1)&3)
__device__ __forceinline__ uint32_t sw64_off(int row, int c) {
    return (uint32_t)(row * 64 + ((c ^ ((row >> 1) & 3)) << 4));
}

// MUFU tanh for the score epilogue (2 MUFU + few ALU; MUFU pipe idle there).
__device__ __forceinline__ float tanh_mufu(float x) {
    float ax = fabsf(x);
    float e  = __expf(2.0f * ax);                 // inf for big ax -> t = 1
    float t  = 1.0f - __fdividef(2.0f, e + 1.0f);
    return copysignf(t, x);
}

// ---------------------------------------------------------------------------
// split values fp32 -> tiled pre-swizzled fp16
// ---------------------------------------------------------------------------
__global__ void split_values_kernel(const float* __restrict__ v) {
    size_t i = ((size_t)blockIdx.x * 256 + threadIdx.x) * 4;
    float4 x = *(const float4*)(v + i);
    const int row = (int)(i >> 10), col = (int)(i & 1023);
    const int rb = row >> 7, r = row & 127;
    const int ch = col >> 5,  ci = col & 31;
    const int sw = (ci >> 3) ^ ((r >> 1) & 3);
    unsigned char* base = g_at + ((size_t)(rb * NCHUNK + ch) * CHUNK_A)
                               + r * 64 + sw * 16 + (ci & 7) * 2;
    __half2 a = __halves2half2(__float2half_rn(x.x), __float2half_rn(x.y));
    __half2 b = __halves2half2(__float2half_rn(x.z), __float2half_rn(x.w));
    uint2 hi;
    hi.x = *(uint32_t*)&a; hi.y = *(uint32_t*)&b;
    *(uint2*)base = hi;
}

// ---------------------------------------------------------------------------
// W1 [k][u] -> tiled pre-swizzled transposed fp16
// ---------------------------------------------------------------------------
__global__ void split_w1t_kernel(const float* __restrict__ W1) {
    __shared__ float t[32][33];
    const int bx = blockIdx.x * 32, by = blockIdx.y * 32;  // bx: u, by: k
    const int tx = threadIdx.x, ty = threadIdx.y;
#pragma unroll
    for (int rr = 0; rr < 4; ++rr)
        t[ty + 8 * rr][tx] = W1[(size_t)(by + ty + 8 * rr) * UN + bx + tx];
    __syncthreads();
    const int u = bx + tx, k0 = by + ty * 4;
    float4 x;
    x.x = t[ty * 4 + 0][tx]; x.y = t[ty * 4 + 1][tx];
    x.z = t[ty * 4 + 2][tx]; x.w = t[ty * 4 + 3][tx];
    const int ut = u >> 7, r = u & 127;
    const int ch = k0 >> 5, ci = k0 & 31;
    const int sw = (ci >> 3) ^ ((r >> 1) & 3);
    unsigned char* base = g_bt + ((size_t)(ut * NCHUNK + ch) * CHUNK_B)
                               + r * 64 + sw * 16 + (ci & 7) * 2;
    __half2 a = __halves2half2(__float2half_rn(x.x), __float2half_rn(x.y));
    __half2 b = __halves2half2(__float2half_rn(x.z), __float2half_rn(x.w));
    uint2 hi;
    hi.x = *(uint32_t*)&a; hi.y = *(uint32_t*)&b;
    *(uint2*)base = hi;
}

// ---------------------------------------------------------------------------
__global__ void projq_kernel(const float* __restrict__ q,
                             const float* __restrict__ W2,
                             const float* __restrict__ b2) {
    const int u = blockIdx.x * 256 + threadIdx.x;
    const int b = blockIdx.y;
    const float* qb = q + b * DQ;
    float acc = b2[u];
#pragma unroll 8
    for (int d = 0; d < DQ; ++d)
        acc = fmaf(qb[d], W2[(size_t)d * UN + u], acc);
    g_projq[b * UN + u] = acc;
}

// ---------------------------------------------------------------------------
// score: fp16 single-pass HMMA, producer warp, 3-stage x 64-k pipeline.
// 288 threads: warps 0-7 compute (64x32 warp tiles), warp 8 producer.
// Stage released after the last kslice's LDSMs (reads issued), not its MMAs.
// ---------------------------------------------------------------------------
__global__ __launch_bounds__(288, 2) void score_kernel(
    const float* __restrict__ b1g, const float* __restrict__ Vv) {

    extern __shared__ char smem[];
    const uint32_t sb    = smem_u32(smem);
    const uint32_t FULLB = sb;          // full[st]  at sb + st*8
    const uint32_t EMPTB = sb + 24;     // empty[st] at sb + 24 + st*8
    const uint32_t SDATA = sb + 1024;

    const int tid = threadIdx.x, wid = tid >> 5, lane = tid & 31;
    const int u0   = blockIdx.x * BN;
    const int row0 = blockIdx.y * BM;
    const int b    = row0 >> 11;
    const int warp_m = wid & 1, warp_n = wid >> 1;   // valid for wid<8

    const unsigned char* gA = g_at + (size_t)blockIdx.y * NCHUNK * CHUNK_A;
    const unsigned char* gB = g_bt + (size_t)blockIdx.x * NCHUNK * CHUNK_B;

    if (tid == 0) {
#pragma unroll
        for (int st = 0; st < NSTAGE; ++st) {
            MBARRIER_INIT(FULLB + st * 8, 1);
            MBARRIER_INIT(EMPTB + st * 8, 8);
        }
        FENCE_PROXY_ASYNC();
    }
    __syncthreads();

    if (wid == 8) {
        // ---------------- producer warp -------------------------------------
        if (lane == 0) {
            int st = 0, r = 0;
            for (int t = 0; t < NSTEP; ++t) {
                if (t >= NSTAGE) MBARRIER_WAIT(EMPTB + st * 8, (r - 1) & 1);
                const uint32_t dst = SDATA + st * STAGE_BYTES;
                MBARRIER_EXPECT_TX(FULLB + st * 8, STAGE_BYTES);
                cp_bulk(dst,         gA + (size_t)t * 16384, 16384, FULLB + st * 8);
                cp_bulk(dst + 16384, gB + (size_t)t * 16384, 16384, FULLB + st * 8);
                if (++st == NSTAGE) { st = 0; ++r; }
            }
        }
    } else {
        // ---------------- compute warps -------------------------------------
        const int lr = lane & 15, lh = lane >> 4;
        uint32_t aoff[4], boff[2];
#pragma unroll
        for (int mt = 0; mt < 4; ++mt)
            aoff[mt] = sw64_off(warp_m * 64 + mt * 16 + lr, lh);
#pragma unroll
        for (int bt = 0; bt < 2; ++bt)
            boff[bt] = sw64_off(warp_n * 32 + bt * 16 + lr, lh);

        float acc[4][4][4];
#pragma unroll
        for (int i = 0; i < 4; ++i)
#pragma unroll
            for (int j = 0; j < 4; ++j)
#pragma unroll
                for (int k = 0; k < 4; ++k) acc[i][j][k] = 0.0f;

        int st = 0, rnd = 0;
        for (int s = 0; s < NSTEP; ++s) {
            const uint32_t sb_cp = SDATA + st * STAGE_BYTES;
            MBARRIER_WAIT(FULLB + st * 8, rnd & 1);

#pragma unroll
            for (int kslice = 0; kslice < 4; ++kslice) {
                const uint32_t sub = (kslice >> 1) * 8192;
                const uint32_t kx  = (kslice & 1) << 5;
                const uint32_t abase = sb_cp + sub;
                uint32_t a[4][4], bh[2][4];
#pragma unroll
                for (int mt = 0; mt < 4; ++mt)
                    LDSM_X4(a[mt], abase + (aoff[mt] ^ kx));
#pragma unroll
                for (int bt = 0; bt < 2; ++bt)
                    LDSM_X4(bh[bt], abase + 16384 + (boff[bt] ^ kx));
                // last kslice: all stage reads issued -> release the stage
                if (kslice == 3 && lane == 0) MBARRIER_ARRIVE(EMPTB + st * 8);
#pragma unroll
                for (int mt = 0; mt < 4; ++mt)
#pragma unroll
                    for (int nt = 0; nt < 4; ++nt)
                        MMA16816(acc[mt][nt], a[mt],
                                 bh[nt >> 1][nt & 1], bh[nt >> 1][(nt & 1) + 2]);
            }
            if (++st == NSTAGE) { st = 0; ++rnd; }
        }

        __syncthreads();   // joins producer sync below

        // ---------------- fused epilogue (MUFU tanh) ------------------------
        float tb[8], tv[8];
#pragma unroll
        for (int nt = 0; nt < 4; ++nt)
#pragma unroll
            for (int par = 0; par < 2; ++par) {
                const int u = u0 + warp_n * 32 + nt * 8 + (lane & 3) * 2 + par;
                tb[nt * 2 + par] = b1g[u] + g_projq[b * UN + u];
                tv[nt * 2 + par] = Vv[u];
            }

        float* red = (float*)(smem + 1024);
#pragma unroll
        for (int mt = 0; mt < 4; ++mt) {
            float s0 = 0.0f, s1 = 0.0f;
#pragma unroll
            for (int nt = 0; nt < 4; ++nt)
#pragma unroll
                for (int par = 0; par < 2; ++par) {
                    const int j = nt * 2 + par;
                    s0 = fmaf(tanh_mufu(acc[mt][nt][par]     + tb[j]), tv[j], s0);
                    s1 = fmaf(tanh_mufu(acc[mt][nt][2 + par] + tb[j]), tv[j], s1);
                }
            s0 += __shfl_xor_sync(0xffffffff, s0, 1);
            s0 += __shfl_xor_sync(0xffffffff, s0, 2);
            s1 += __shfl_xor_sync(0xffffffff, s1, 1);
            s1 += __shfl_xor_sync(0xffffffff, s1, 2);
            if ((lane & 3) == 0) {
                const int r = warp_m * 64 + mt * 16 + (lane >> 2);
                red[r * 4 + warp_n]       = s0;
                red[(r + 8) * 4 + warp_n] = s1;
            }
        }
    }
    if (wid == 8) __syncthreads();   // producer joins first barrier
    __syncthreads();                  // red[] complete
    if (tid < 128) {
        float* red = (float*)(smem + 1024);
        const float s = (red[tid * 4 + 0] + red[tid * 4 + 1]) +
                        (red[tid * 4 + 2] + red[tid * 4 + 3]);
        g_spart[(size_t)(row0 + tid) * 8 + blockIdx.x] = s;
    }
}

// ---------------------------------------------------------------------------
__global__ void softmax_kernel(float* __restrict__ out_w) {
    const int b = blockIdx.x, tid = threadIdx.x;
    __shared__ float sm[256];
    float v[8];
    float lmax = -1e30f;
#pragma unroll
    for (int i = 0; i < 8; ++i) {
        const float* p = g_spart + (size_t)(b * SEQ + tid + i * 256) * 8;
        v[i] = ((p[0] + p[1]) + (p[2] + p[3])) + ((p[4] + p[5]) + (p[6] + p[7]));
        lmax = fmaxf(lmax, v[i]);
    }
    sm[tid] = lmax; __syncthreads();
    for (int s = 128; s > 0; s >>= 1) {
        if (tid < s) sm[tid] = fmaxf(sm[tid], sm[tid + s]);
        __syncthreads();
    }
    const float m = sm[0]; __syncthreads();
    float lsum = 0.0f;
#pragma unroll
    for (int i = 0; i < 8; ++i) { v[i] = __expf(v[i] - m); lsum += v[i]; }
    sm[tid] = lsum; __syncthreads();
    for (int s = 128; s > 0; s >>= 1) {
        if (tid < s) sm[tid] += sm[tid + s];
        __syncthreads();
    }
    const float inv = 1.0f / sm[0];
#pragma unroll
    for (int i = 0; i < 8; ++i)
        out_w[b * SEQ + tid + i * 256] = v[i] * inv;
}

// ---------------------------------------------------------------------------
__global__ void ctx_part_kernel(const float* __restrict__ values,
                                const float* __restrict__ w) {
    __shared__ float ws[32];
    const int sc = blockIdx.x, b = blockIdx.y, tid = threadIdx.x;
    if (tid < 32) ws[tid] = w[b * SEQ + sc * 32 + tid];
    __syncthreads();
    const int d0 = tid * 4;
    const float* base = values + (size_t)b * SEQ * DV + (size_t)sc * 32 * DV + d0;
    float4 acc = make_float4(0.f, 0.f, 0.f, 0.f);
#pragma unroll 8
    for (int s = 0; s < 32; ++s) {
        const float4 v = *(const float4*)(base + (size_t)s * DV);
        const float x = ws[s];
        acc.x = fmaf(x, v.x, acc.x); acc.y = fmaf(x, v.y, acc.y);
        acc.z = fmaf(x, v.z, acc.z); acc.w = fmaf(x, v.w, acc.w);
    }
    *(float4*)(g_cpart + (size_t)(sc * BATCH + b) * DV + d0) = acc;
}

__global__ void ctx_reduce_kernel(float* __restrict__ out_c) {
    const int idx = blockIdx.x * 256 + threadIdx.x;
    const int bb = idx >> 10, dd = idx & 1023;
    float s = 0.0f;
#pragma unroll 8
    for (int c = 0; c < NCTX; ++c)
        s += g_cpart[(size_t)(c * BATCH + bb) * DV + dd];
    out_c[idx] = s;
}

// ---------------------------------------------------------------------------
extern "C" void kernel_launch(void* const* d_in, const int* in_sizes, int n_in,
                              void* d_out, int out_size) {
    const float* query  = (const float*)d_in[0];
    const float* values = (const float*)d_in[1];
    const float* W1     = (const float*)d_in[2];
    const float* b1     = (const float*)d_in[3];
    const float* W2     = (const float*)d_in[4];
    const float* b2     = (const float*)d_in[5];
    const float* Vv     = (const float*)d_in[6];
    // d_in[7] = bV: cancels in softmax.

    float* out_c = (float*)d_out;
    float* out_w = out_c + BATCH * DV;

    static bool attr_set = false;
    if (!attr_set) {
        cudaFuncSetAttribute(score_kernel,
                             cudaFuncAttributeMaxDynamicSharedMemorySize, SMEM_BYTES);
        attr_set = true;
    }

    split_values_kernel<<<65536, 256>>>(values);
    split_w1t_kernel<<<dim3(32, 32), dim3(32, 8)>>>(W1);
    projq_kernel<<<dim3(4, BATCH), 256>>>(query, W2, b2);
    score_kernel<<<dim3(8, 512), 288, SMEM_BYTES>>>(b1, Vv);
    softmax_kernel<<<BATCH, 256>>>(out_w);
    ctx_part_kernel<<<dim3(NCTX, BATCH), 256>>>(values, out_w);
    ctx_reduce_kernel<<<128, 256>>>(out_c);
}

// round 11
// speedup vs baseline: 1.1622x; 1.0715x over previous
#include <cuda_runtime.h>
#include <cuda_fp16.h>
#include <math.h>
#include <stdint.h>

#define BATCH 32
#define SEQ   2048
#define DQ    1024
#define DV    1024
#define UN    1024
#define ROWS  (BATCH * SEQ)

#define BM 128
#define BN 128
#define CHUNK_A 8192                  // per 32-k sub-chunk
#define CHUNK_B 8192
#define NCHUNK (DV / 32)              // 32 sub-chunks
#define NSTEP  16                     // stages consumed (2 sub-chunks each)
#define STAGE_BYTES 32768             // A 16K | B 16K
#define NSTAGE 3
#define SMEM_BYTES (1024 + NSTAGE * STAGE_BYTES)   // 99328
#define NCTX 64

// prep kernel grid partition
#define PREP_SPLIT_BLOCKS 32768
#define PREP_W1T_BLOCKS   1024
#define PREP_PROJQ_BLOCKS 128
#define PREP_BLOCKS (PREP_SPLIT_BLOCKS + PREP_W1T_BLOCKS + PREP_PROJQ_BLOCKS)

// ---------------- device scratch ------------------------------------------
__device__ unsigned char g_at[(size_t)(ROWS / BM) * NCHUNK * CHUNK_A];  // 128MB
__device__ unsigned char g_bt[(size_t)(UN / BN) * NCHUNK * CHUNK_B];    // 2MB
__device__ float g_projq[BATCH * UN];
__device__ float g_spart[(size_t)ROWS * 8];
__device__ float g_cpart[(size_t)NCTX * BATCH * DV];

// ---------------- helpers ---------------------------------------------------
__device__ __forceinline__ uint32_t smem_u32(const void* p) {
    uint32_t a;
    asm("{ .reg .u64 t; cvta.to.shared.u64 t, %1; cvt.u32.u64 %0, t; }" : "=r"(a) : "l"(p));
    return a;
}
#define MBARRIER_INIT(addr, cnt) \
    asm volatile("mbarrier.init.shared.b64 [%0], %1;" :: "r"((uint32_t)(addr)), "r"((uint32_t)(cnt)) : "memory")
#define MBARRIER_ARRIVE(addr) \
    asm volatile("mbarrier.arrive.shared.b64 _, [%0];" :: "r"((uint32_t)(addr)) : "memory")
#define MBARRIER_EXPECT_TX(addr, tx) \
    asm volatile("mbarrier.arrive.expect_tx.shared.b64 _, [%0], %1;" :: "r"((uint32_t)(addr)), "r"((uint32_t)(tx)) : "memory")
#define MBARRIER_WAIT(addr, ph) do { \
    uint32_t _m = (uint32_t)(addr), _p = (uint32_t)(ph), _d; \
    asm volatile("{\n\t.reg .pred p;\n\t" \
        "mbarrier.try_wait.parity.acquire.cta.shared::cta.b64 p, [%1], %2;\n\t" \
        "selp.b32 %0, 1, 0, p;\n\t}" : "=r"(_d) : "r"(_m), "r"(_p) : "memory"); \
    if (!_d) { \
        asm volatile("{\n\t.reg .pred P1;\n\t" \
            "WL_%=:\n\t" \
            "mbarrier.try_wait.parity.acquire.cta.shared::cta.b64 P1, [%0], %1, 0x989680;\n\t" \
            "@P1 bra.uni WD_%=;\n\t" \
            "bra.uni WL_%=;\n\t" \
            "WD_%=:\n\t}" :: "r"(_m), "r"(_p) : "memory"); \
    } \
} while (0)
#define FENCE_PROXY_ASYNC() asm volatile("fence.proxy.async.shared::cta;" ::: "memory")
__device__ __forceinline__ void cp_bulk(uint32_t dst, const void* src, uint32_t bytes,
                                        uint32_t mbar) {
    asm volatile("cp.async.bulk.shared::cta.global.mbarrier::complete_tx::bytes "
                 "[%0], [%1], %2, [%3];"
                 :: "r"(dst), "l"(src), "r"(bytes), "r"(mbar) : "memory");
}
#define LDSM_X4(R, addr) \
    asm volatile("ldmatrix.sync.aligned.m8n8.x4.shared.b16 {%0,%1,%2,%3}, [%4];" \
        : "=r"((R)[0]), "=r"((R)[1]), "=r"((R)[2]), "=r"((R)[3]) : "r"(addr))
#define MMA16816(C, A, B0, B1) \
    asm volatile("mma.sync.aligned.m16n8k16.row.col.f32.f16.f16.f32 " \
        "{%0,%1,%2,%3},{%4,%5,%6,%7},{%8,%9},{%0,%1,%2,%3};" \
        : "+f"((C)[0]), "+f"((C)[1]), "+f"((C)[2]), "+f"((C)[3]) \
        : "r"((A)[0]), "r"((A)[1]), "r"((A)[2]), "r"((A)[3]), "r"(B0), "r"(B1))

// SW64 swizzle: 64B rows; 16B chunk c of row r -> c ^ ((r>>1)&3)
__device__ __forceinline__ uint32_t sw64_off(int row, int c) {
    return (uint32_t)(row * 64 + ((c ^ ((row >> 1) & 3)) << 4));
}

// MUFU tanh for the score epilogue (2 MUFU + few ALU; MUFU pipe idle there).
__device__ __forceinline__ float tanh_mufu(float x) {
    float ax = fabsf(x);
    float e  = __expf(2.0f * ax);                 // inf for big ax -> t = 1
    float t  = 1.0f - __fdividef(2.0f, e + 1.0f);
    return copysignf(t, x);
}

// ---------------------------------------------------------------------------
// merged prep kernel: split values | split+transpose W1 | proj_q
// ---------------------------------------------------------------------------
__global__ void prep_kernel(const float* __restrict__ v,
                            const float* __restrict__ W1,
                            const float* __restrict__ q,
                            const float* __restrict__ W2,
                            const float* __restrict__ b2) {
    const int bid = blockIdx.x;
    const int tid = threadIdx.x;

    if (bid < PREP_SPLIT_BLOCKS) {
        // ---- split values fp32 -> tiled pre-swizzled fp16 (8 elems/thread) --
        size_t i = ((size_t)bid * 256 + tid) * 8;
        float4 x0 = *(const float4*)(v + i);
        float4 x1 = *(const float4*)(v + i + 4);
        const int row = (int)(i >> 10), col = (int)(i & 1023);
        const int rb = row >> 7, r = row & 127;
        const int ch = col >> 5, ci = col & 31;
        const int c  = ci >> 3;                       // exact 16B chunk
        const int sw = c ^ ((r >> 1) & 3);
        unsigned char* base = g_at + ((size_t)(rb * NCHUNK + ch) * CHUNK_A)
                                   + r * 64 + sw * 16;
        __half2 a0 = __halves2half2(__float2half_rn(x0.x), __float2half_rn(x0.y));
        __half2 a1 = __halves2half2(__float2half_rn(x0.z), __float2half_rn(x0.w));
        __half2 a2 = __halves2half2(__float2half_rn(x1.x), __float2half_rn(x1.y));
        __half2 a3 = __halves2half2(__float2half_rn(x1.z), __float2half_rn(x1.w));
        uint4 out;
        out.x = *(uint32_t*)&a0; out.y = *(uint32_t*)&a1;
        out.z = *(uint32_t*)&a2; out.w = *(uint32_t*)&a3;
        *(uint4*)base = out;
    } else if (bid < PREP_SPLIT_BLOCKS + PREP_W1T_BLOCKS) {
        // ---- W1 [k][u] -> tiled pre-swizzled transposed fp16 ---------------
        __shared__ float t[32][33];
        const int b2d = bid - PREP_SPLIT_BLOCKS;
        const int bx = (b2d & 31) * 32, by = (b2d >> 5) * 32;  // bx: u, by: k
        const int tx = tid & 31, ty = tid >> 5;
#pragma unroll
        for (int rr = 0; rr < 4; ++rr)
            t[ty + 8 * rr][tx] = W1[(size_t)(by + ty + 8 * rr) * UN + bx + tx];
        __syncthreads();
        const int u = bx + tx, k0 = by + ty * 4;
        float4 x;
        x.x = t[ty * 4 + 0][tx]; x.y = t[ty * 4 + 1][tx];
        x.z = t[ty * 4 + 2][tx]; x.w = t[ty * 4 + 3][tx];
        const int ut = u >> 7, r = u & 127;
        const int ch = k0 >> 5, ci = k0 & 31;
        const int sw = (ci >> 3) ^ ((r >> 1) & 3);
        unsigned char* base = g_bt + ((size_t)(ut * NCHUNK + ch) * CHUNK_B)
                                   + r * 64 + sw * 16 + (ci & 7) * 2;
        __half2 a = __halves2half2(__float2half_rn(x.x), __float2half_rn(x.y));
        __half2 b = __halves2half2(__float2half_rn(x.z), __float2half_rn(x.w));
        uint2 hi;
        hi.x = *(uint32_t*)&a; hi.y = *(uint32_t*)&b;
        *(uint2*)base = hi;
    } else {
        // ---- proj_q[b,u] = query[b,:] . W2[:,u] + b2[u] ---------------------
        const int b3 = bid - PREP_SPLIT_BLOCKS - PREP_W1T_BLOCKS;
        const int u = (b3 & 3) * 256 + tid;
        const int b = b3 >> 2;
        const float* qb = q + b * DQ;
        float acc = b2[u];
#pragma unroll 8
        for (int d = 0; d < DQ; ++d)
            acc = fmaf(qb[d], W2[(size_t)d * UN + u], acc);
        g_projq[b * UN + u] = acc;
    }
}

// ---------------------------------------------------------------------------
// score: fp16 single-pass HMMA, producer warp, 3-stage x 64-k pipeline.
// 288 threads: warps 0-7 compute (64x32 warp tiles), warp 8 producer.
// ---------------------------------------------------------------------------
__global__ __launch_bounds__(288, 2) void score_kernel(
    const float* __restrict__ b1g, const float* __restrict__ Vv) {

    extern __shared__ char smem[];
    const uint32_t sb    = smem_u32(smem);
    const uint32_t FULLB = sb;          // full[st]  at sb + st*8
    const uint32_t EMPTB = sb + 24;     // empty[st] at sb + 24 + st*8
    const uint32_t SDATA = sb + 1024;

    const int tid = threadIdx.x, wid = tid >> 5, lane = tid & 31;
    const int u0   = blockIdx.x * BN;
    const int row0 = blockIdx.y * BM;
    const int b    = row0 >> 11;
    const int warp_m = wid & 1, warp_n = wid >> 1;   // valid for wid<8

    const unsigned char* gA = g_at + (size_t)blockIdx.y * NCHUNK * CHUNK_A;
    const unsigned char* gB = g_bt + (size_t)blockIdx.x * NCHUNK * CHUNK_B;

    if (tid == 0) {
#pragma unroll
        for (int st = 0; st < NSTAGE; ++st) {
            MBARRIER_INIT(FULLB + st * 8, 1);
            MBARRIER_INIT(EMPTB + st * 8, 8);
        }
        FENCE_PROXY_ASYNC();
    }
    __syncthreads();

    if (wid == 8) {
        // ---------------- producer warp -------------------------------------
        if (lane == 0) {
            int st = 0, r = 0;
            for (int t = 0; t < NSTEP; ++t) {
                if (t >= NSTAGE) MBARRIER_WAIT(EMPTB + st * 8, (r - 1) & 1);
                const uint32_t dst = SDATA + st * STAGE_BYTES;
                MBARRIER_EXPECT_TX(FULLB + st * 8, STAGE_BYTES);
                cp_bulk(dst,         gA + (size_t)t * 16384, 16384, FULLB + st * 8);
                cp_bulk(dst + 16384, gB + (size_t)t * 16384, 16384, FULLB + st * 8);
                if (++st == NSTAGE) { st = 0; ++r; }
            }
        }
    } else {
        // ---------------- compute warps -------------------------------------
        const int lr = lane & 15, lh = lane >> 4;
        uint32_t aoff[4], boff[2];
#pragma unroll
        for (int mt = 0; mt < 4; ++mt)
            aoff[mt] = sw64_off(warp_m * 64 + mt * 16 + lr, lh);
#pragma unroll
        for (int bt = 0; bt < 2; ++bt)
            boff[bt] = sw64_off(warp_n * 32 + bt * 16 + lr, lh);

        float acc[4][4][4];
#pragma unroll
        for (int i = 0; i < 4; ++i)
#pragma unroll
            for (int j = 0; j < 4; ++j)
#pragma unroll
                for (int k = 0; k < 4; ++k) acc[i][j][k] = 0.0f;

        int st = 0, rnd = 0;
        for (int s = 0; s < NSTEP; ++s) {
            const uint32_t sb_cp = SDATA + st * STAGE_BYTES;
            MBARRIER_WAIT(FULLB + st * 8, rnd & 1);

#pragma unroll
            for (int kslice = 0; kslice < 4; ++kslice) {
                const uint32_t sub = (kslice >> 1) * 8192;
                const uint32_t kx  = (kslice & 1) << 5;
                const uint32_t abase = sb_cp + sub;
                uint32_t a[4][4], bh[2][4];
#pragma unroll
                for (int mt = 0; mt < 4; ++mt)
                    LDSM_X4(a[mt], abase + (aoff[mt] ^ kx));
#pragma unroll
                for (int bt = 0; bt < 2; ++bt)
                    LDSM_X4(bh[bt], abase + 16384 + (boff[bt] ^ kx));
                // last kslice: all stage reads issued -> release the stage
                if (kslice == 3 && lane == 0) MBARRIER_ARRIVE(EMPTB + st * 8);
#pragma unroll
                for (int mt = 0; mt < 4; ++mt)
#pragma unroll
                    for (int nt = 0; nt < 4; ++nt)
                        MMA16816(acc[mt][nt], a[mt],
                                 bh[nt >> 1][nt & 1], bh[nt >> 1][(nt & 1) + 2]);
            }
            if (++st == NSTAGE) { st = 0; ++rnd; }
        }

        __syncthreads();   // joins producer sync below

        // ---------------- fused epilogue (MUFU tanh) ------------------------
        float tb[8], tv[8];
#pragma unroll
        for (int nt = 0; nt < 4; ++nt)
#pragma unroll
            for (int par = 0; par < 2; ++par) {
                const int u = u0 + warp_n * 32 + nt * 8 + (lane & 3) * 2 + par;
                tb[nt * 2 + par] = b1g[u] + g_projq[b * UN + u];
                tv[nt * 2 + par] = Vv[u];
            }

        float* red = (float*)(smem + 1024);
#pragma unroll
        for (int mt = 0; mt < 4; ++mt) {
            float s0 = 0.0f, s1 = 0.0f;
#pragma unroll
            for (int nt = 0; nt < 4; ++nt)
#pragma unroll
                for (int par = 0; par < 2; ++par) {
                    const int j = nt * 2 + par;
                    s0 = fmaf(tanh_mufu(acc[mt][nt][par]     + tb[j]), tv[j], s0);
                    s1 = fmaf(tanh_mufu(acc[mt][nt][2 + par] + tb[j]), tv[j], s1);
                }
            s0 += __shfl_xor_sync(0xffffffff, s0, 1);
            s0 += __shfl_xor_sync(0xffffffff, s0, 2);
            s1 += __shfl_xor_sync(0xffffffff, s1, 1);
            s1 += __shfl_xor_sync(0xffffffff, s1, 2);
            if ((lane & 3) == 0) {
                const int r = warp_m * 64 + mt * 16 + (lane >> 2);
                red[r * 4 + warp_n]       = s0;
                red[(r + 8) * 4 + warp_n] = s1;
            }
        }
    }
    if (wid == 8) __syncthreads();   // producer joins first barrier
    __syncthreads();                  // red[] complete
    if (tid < 128) {
        float* red = (float*)(smem + 1024);
        const float s = (red[tid * 4 + 0] + red[tid * 4 + 1]) +
                        (red[tid * 4 + 2] + red[tid * 4 + 3]);
        g_spart[(size_t)(row0 + tid) * 8 + blockIdx.x] = s;
    }
}

// ---------------------------------------------------------------------------
__global__ void softmax_kernel(float* __restrict__ out_w) {
    const int b = blockIdx.x, tid = threadIdx.x;
    __shared__ float sm[256];
    float v[8];
    float lmax = -1e30f;
#pragma unroll
    for (int i = 0; i < 8; ++i) {
        const float* p = g_spart + (size_t)(b * SEQ + tid + i * 256) * 8;
        v[i] = ((p[0] + p[1]) + (p[2] + p[3])) + ((p[4] + p[5]) + (p[6] + p[7]));
        lmax = fmaxf(lmax, v[i]);
    }
    sm[tid] = lmax; __syncthreads();
    for (int s = 128; s > 0; s >>= 1) {
        if (tid < s) sm[tid] = fmaxf(sm[tid], sm[tid + s]);
        __syncthreads();
    }
    const float m = sm[0]; __syncthreads();
    float lsum = 0.0f;
#pragma unroll
    for (int i = 0; i < 8; ++i) { v[i] = __expf(v[i] - m); lsum += v[i]; }
    sm[tid] = lsum; __syncthreads();
    for (int s = 128; s > 0; s >>= 1) {
        if (tid < s) sm[tid] += sm[tid + s];
        __syncthreads();
    }
    const float inv = 1.0f / sm[0];
#pragma unroll
    for (int i = 0; i < 8; ++i)
        out_w[b * SEQ + tid + i * 256] = v[i] * inv;
}

// ---------------------------------------------------------------------------
// context partial: reads fp16 tiled values (g_at) — half the global traffic.
// Block (sc, b): rows row0p = b*SEQ + sc*32 .. +31; thread owns 4 d's.
// ---------------------------------------------------------------------------
__global__ void ctx_part_kernel(const float* __restrict__ w) {
    __shared__ float ws[32];
    const int sc = blockIdx.x, b = blockIdx.y, tid = threadIdx.x;
    if (tid < 32) ws[tid] = w[b * SEQ + sc * 32 + tid];
    __syncthreads();

    const int d0 = tid * 4;
    const int ch = tid >> 3;                 // d0 >> 5
    const int c  = (tid & 7) >> 1;           // 16B chunk within 64B row
    const int hb = (tid & 1) * 8;            // byte offset inside chunk
    const int row_base = b * SEQ + sc * 32;
    const int rb = row_base >> 7;
    const int r0 = row_base & 127;
    const unsigned char* tile = g_at + ((size_t)(rb * NCHUNK + ch) * CHUNK_A);

    float4 acc = make_float4(0.f, 0.f, 0.f, 0.f);
#pragma unroll 8
    for (int j = 0; j < 32; ++j) {
        const int r = r0 + j;
        const uint2 pk = *(const uint2*)(tile + r * 64
                                         + ((c ^ ((r >> 1) & 3)) << 4) + hb);
        const __half2 h0 = *(const __half2*)&pk.x;
        const __half2 h1 = *(const __half2*)&pk.y;
        const float x = ws[j];
        acc.x = fmaf(x, __low2float(h0),  acc.x);
        acc.y = fmaf(x, __high2float(h0), acc.y);
        acc.z = fmaf(x, __low2float(h1),  acc.z);
        acc.w = fmaf(x, __high2float(h1), acc.w);
    }
    *(float4*)(g_cpart + (size_t)(sc * BATCH + b) * DV + d0) = acc;
}

__global__ void ctx_reduce_kernel(float* __restrict__ out_c) {
    const int idx = blockIdx.x * 256 + threadIdx.x;
    const int bb = idx >> 10, dd = idx & 1023;
    float s = 0.0f;
#pragma unroll 8
    for (int c = 0; c < NCTX; ++c)
        s += g_cpart[(size_t)(c * BATCH + bb) * DV + dd];
    out_c[idx] = s;
}

// ---------------------------------------------------------------------------
extern "C" void kernel_launch(void* const* d_in, const int* in_sizes, int n_in,
                              void* d_out, int out_size) {
    const float* query  = (const float*)d_in[0];
    const float* values = (const float*)d_in[1];
    const float* W1     = (const float*)d_in[2];
    const float* b1     = (const float*)d_in[3];
    const float* W2     = (const float*)d_in[4];
    const float* b2     = (const float*)d_in[5];
    const float* Vv     = (const float*)d_in[6];
    // d_in[7] = bV: cancels in softmax.

    float* out_c = (float*)d_out;
    float* out_w = out_c + BATCH * DV;

    static bool attr_set = false;
    if (!attr_set) {
        cudaFuncSetAttribute(score_kernel,
                             cudaFuncAttributeMaxDynamicSharedMemorySize, SMEM_BYTES);
        attr_set = true;
    }

    prep_kernel<<<PREP_BLOCKS, 256>>>(values, W1, query, W2, b2);
    score_kernel<<<dim3(8, 512), 288, SMEM_BYTES>>>(b1, Vv);
    softmax_kernel<<<BATCH, 256>>>(out_w);
    ctx_part_kernel<<<dim3(NCTX, BATCH), 256>>>(out_w);
    ctx_reduce_kernel<<<128, 256>>>(out_c);
}